// round 8
// baseline (speedup 1.0000x reference)
#include <cuda_runtime.h>
#include <cuda_fp16.h>
#include <cstdint>

// ChebConv K=8 on GB300 (sm_103 base target — mma.sync tensor path):
//  - decode edges (dtype-robust), build padded CSR by dst (1-pass lookback scan)
//  - 7 SpMM propagations: fp16 panel, single-wave persistent blocks with
//    intra-block dynamic node scheduling (L2-byte bound)
//  - GEMM [50000,1024]x[1024,64] via mma.sync fp16, W split hi/lo, + bias+ReLU

#define N_NODES 50000
#define N_EDGES 800000
#define EPAD    (N_EDGES + 4 * N_NODES)
#define F_IN    128
#define F_OUT   64
#define KORD    8
#define KTOT    (KORD * F_IN)                // 1024
#define NKSTEP  (KTOT / 16)                  // 64
#define SCAN_BLK 1024
#define NBLK    ((N_NODES + SCAN_BLK - 1) / SCAN_BLK)   // 49
#define NWARPS_GEMM ((N_NODES + 31) / 32)               // 1563
#define SPMM_BLOCKS 444
#define SPMM_THREADS 512
#define NODES_PER_BLK ((N_NODES + SPMM_BLOCKS - 1) / SPMM_BLOCKS)   // 113

// ---- scratch (static device globals; no allocations) ----
__device__ __align__(16) __half g_T[(size_t)N_NODES * KTOT];   // fp16 panel, slots k*128
__device__ __align__(16) uint4  g_Wpack[NKSTEP * 8 * 32];      // W^T frag {hi01,hi89,lo01,lo89}
__device__ int   g_is64;
__device__ int   g_src[N_EDGES];
__device__ int   g_dst[N_EDGES];
__device__ int   g_cnt[N_NODES];
__device__ int   g_deg[N_NODES];
__device__ float g_dis[N_NODES];
__device__ int   g_rowptr[N_NODES + 1];
__device__ int   g_cursor[N_NODES];
__device__ volatile int g_flag[NBLK];        // lookback status: 0=none, 1=aggregate ready
__device__ volatile int g_bagg[NBLK];        // block aggregate
__device__ __align__(8) int2 g_edge[EPAD];   // {src, float_bits(w)}

// =================== helpers ===============================================
__device__ __forceinline__ void mma16816(float* c, const uint32_t* a, const uint32_t* b) {
    asm volatile(
        "mma.sync.aligned.m16n8k16.row.col.f32.f16.f16.f32 "
        "{%0,%1,%2,%3}, {%4,%5,%6,%7}, {%8,%9}, {%0,%1,%2,%3};"
        : "+f"(c[0]), "+f"(c[1]), "+f"(c[2]), "+f"(c[3])
        : "r"(a[0]), "r"(a[1]), "r"(a[2]), "r"(a[3]), "r"(b[0]), "r"(b[1]));
}
__device__ __forceinline__ uint32_t pack_h2(float a, float b) {
    __half2 h = __floats2half2_rn(a, b);
    return *reinterpret_cast<uint32_t*>(&h);
}
__device__ __forceinline__ float4 unpack_h4(uint2 q) {
    __half2 h0 = *reinterpret_cast<__half2*>(&q.x);
    __half2 h1 = *reinterpret_cast<__half2*>(&q.y);
    float2 f0 = __half22float2(h0), f1 = __half22float2(h1);
    return make_float4(f0.x, f0.y, f1.x, f1.y);
}
__device__ __forceinline__ uint2 pack_h4(float4 r) {
    uint2 q;
    q.x = pack_h2(r.x, r.y);
    q.y = pack_h2(r.z, r.w);
    return q;
}

// ============================ preprocessing ================================
// detect dtype (warp-parallel) + zero histograms + reset lookback flags
__global__ void init_kernel(const unsigned int* __restrict__ p) {
    int i = blockIdx.x * blockDim.x + threadIdx.x;
    if (blockIdx.x == 0 && threadIdx.x < 32) {
        int lane = threadIdx.x;
        bool bad = false;
        #pragma unroll
        for (int j = 0; j < 8; j++)
            if (p[2 * (lane * 8 + j) + 1] != 0u) bad = true;
        unsigned m = __ballot_sync(0xffffffffu, bad);
        if (lane == 0) g_is64 = (m == 0u) ? 1 : 0;
    }
    if (i < NBLK) { g_flag[i] = 0; g_bagg[i] = 0; }
    if (i < N_NODES) { g_cnt[i] = 0; g_deg[i] = 0; }
}
__global__ void decode_hist_kernel(const void* __restrict__ ei) {
    int e = blockIdx.x * blockDim.x + threadIdx.x;
    if (e < N_EDGES) {
        int s, d;
        if (g_is64) {
            const long long* p = (const long long*)ei;
            s = (int)p[e]; d = (int)p[N_EDGES + e];
        } else {
            const int* p = (const int*)ei;
            s = p[e]; d = p[N_EDGES + e];
        }
        s = min(max(s, 0), N_NODES - 1);
        d = min(max(d, 0), N_NODES - 1);
        g_src[e] = s; g_dst[e] = d;
        atomicAdd(&g_deg[s], 1);
        atomicAdd(&g_cnt[d], 1);
    }
}
// one-pass scan with chain lookback; also writes dis, cursor, padding edges
__global__ void scan_kernel() {
    __shared__ int wsum[32];
    __shared__ int s_boff;
    int tid = threadIdx.x, lane = tid & 31, wid = tid >> 5;
    int i = blockIdx.x * SCAN_BLK + tid;
    int cnt = 0, v = 0;
    if (i < N_NODES) {
        int d = g_deg[i];
        g_dis[i] = (d > 0) ? rsqrtf((float)d) : 0.0f;
        cnt = g_cnt[i];
        v = (cnt + 3) & ~3;                  // pad row to multiple of 4
    }
    int x = v;
    #pragma unroll
    for (int off = 1; off < 32; off <<= 1) {
        int t = __shfl_up_sync(0xffffffffu, x, off);
        if (lane >= off) x += t;
    }
    if (lane == 31) wsum[wid] = x;
    __syncthreads();
    if (wid == 0) {
        int y = wsum[lane];
        #pragma unroll
        for (int off = 1; off < 32; off <<= 1) {
            int t = __shfl_up_sync(0xffffffffu, y, off);
            if (lane >= off) y += t;
        }
        wsum[lane] = y;
    }
    __syncthreads();
    int agg = wsum[31];
    // publish aggregate, then chain-lookback previous blocks
    if (tid == 0) {
        g_bagg[blockIdx.x] = agg;
        __threadfence();
        g_flag[blockIdx.x] = 1;
        int off = 0;
        for (int b = 0; b < (int)blockIdx.x; b++) {
            while (g_flag[b] == 0) { }
            off += g_bagg[b];
        }
        s_boff = off;
        if (blockIdx.x == NBLK - 1) g_rowptr[N_NODES] = off + agg;
    }
    __syncthreads();
    int excl = s_boff + x - v + (wid > 0 ? wsum[wid - 1] : 0);
    if (i < N_NODES) {
        g_rowptr[i] = excl;
        g_cursor[i] = excl;
        int cntp = (cnt + 3) & ~3;
        for (int j = cnt; j < cntp; j++)
            g_edge[excl + j] = make_int2(0, 0);
    }
}
__global__ void scatter_kernel() {
    int e = blockIdx.x * blockDim.x + threadIdx.x;
    if (e < N_EDGES) {
        int s = g_src[e];
        int d = g_dst[e];
        float w = -g_dis[s] * g_dis[d];
        int pos = atomicAdd(&g_cursor[d], 1);
        g_edge[pos] = make_int2(s, __float_as_int(w));
    }
}
// fused: blocks [0,64) pack W^T hi/lo fragments; blocks [64,...) convert x -> fp16 slot 0
#define PACKW_BLOCKS 64
__global__ void prep_kernel(const float* __restrict__ W, const float* __restrict__ x) {
    if (blockIdx.x < PACKW_BLOCKS) {
        int i = blockIdx.x * 256 + threadIdx.x;      // < 16384
        int lane = i & 31, nt = (i >> 5) & 7, ks = i >> 8;
        int n  = nt * 8 + (lane >> 2);
        int k0 = ks * 16 + (lane & 3) * 2;
        float v00 = W[(size_t)(k0    ) * 64 + n];
        float v01 = W[(size_t)(k0 + 1) * 64 + n];
        float v10 = W[(size_t)(k0 + 8) * 64 + n];
        float v11 = W[(size_t)(k0 + 9) * 64 + n];
        __half h00 = __float2half_rn(v00), h01 = __float2half_rn(v01);
        __half h10 = __float2half_rn(v10), h11 = __float2half_rn(v11);
        uint4 p;
        __half2 a = __halves2half2(h00, h01);
        __half2 b = __halves2half2(h10, h11);
        p.x = *reinterpret_cast<uint32_t*>(&a);
        p.y = *reinterpret_cast<uint32_t*>(&b);
        p.z = pack_h2(v00 - __half2float(h00), v01 - __half2float(h01));
        p.w = pack_h2(v10 - __half2float(h10), v11 - __half2float(h11));
        g_Wpack[i] = p;
    } else {
        int i = (blockIdx.x - PACKW_BLOCKS) * 256 + threadIdx.x;  // float4 index
        if (i < N_NODES * (F_IN / 4)) {
            int row = i >> 5, c4 = i & 31;
            float4 v = __ldg((const float4*)x + i);
            *(uint2*)&g_T[(size_t)row * KTOT + c4 * 4] = pack_h4(v);   // slot 0
        }
    }
}

// ============================== SpMM =======================================
// single-wave persistent blocks; block owns a node range; 16 warps pull nodes
// from a shared-memory counter (dynamic balance). 32 lanes x 4 fp16 features.
// mode 0: T_out = prop(T_in);  mode 1: T_out = 2*prop(T_in) - T_prev
__global__ void __launch_bounds__(SPMM_THREADS) spmm_kernel(
        int slot_in, int slot_prev, int slot_out, int mode) {
    __shared__ int s_next;
    int lane = threadIdx.x & 31;
    int base = blockIdx.x * NODES_PER_BLK;
    int lim  = min(base + NODES_PER_BLK, N_NODES);
    if (threadIdx.x == 0) s_next = base;
    __syncthreads();
    int cin = slot_in * F_IN;

    for (;;) {
        int n;
        if (lane == 0) n = atomicAdd(&s_next, 1);
        n = __shfl_sync(0xffffffffu, n, 0);
        if (n >= lim) break;

        int beg = g_rowptr[n], end = g_rowptr[n + 1];
        float4 acc = make_float4(0.f, 0.f, 0.f, 0.f);
        #pragma unroll 2
        for (int e = beg; e < end; e += 4) {
            int2 ed0 = __ldg(&g_edge[e]);
            int2 ed1 = __ldg(&g_edge[e + 1]);
            int2 ed2 = __ldg(&g_edge[e + 2]);
            int2 ed3 = __ldg(&g_edge[e + 3]);
            uint2 q0 = __ldg((const uint2*)(g_T + (size_t)ed0.x * KTOT + cin) + lane);
            uint2 q1 = __ldg((const uint2*)(g_T + (size_t)ed1.x * KTOT + cin) + lane);
            uint2 q2 = __ldg((const uint2*)(g_T + (size_t)ed2.x * KTOT + cin) + lane);
            uint2 q3 = __ldg((const uint2*)(g_T + (size_t)ed3.x * KTOT + cin) + lane);
            float w0 = __int_as_float(ed0.y), w1 = __int_as_float(ed1.y);
            float w2 = __int_as_float(ed2.y), w3 = __int_as_float(ed3.y);
            float4 v0 = unpack_h4(q0);
            float4 v1 = unpack_h4(q1);
            float4 v2 = unpack_h4(q2);
            float4 v3 = unpack_h4(q3);
            acc.x += w0 * v0.x + w1 * v1.x + w2 * v2.x + w3 * v3.x;
            acc.y += w0 * v0.y + w1 * v1.y + w2 * v2.y + w3 * v3.y;
            acc.z += w0 * v0.z + w1 * v1.z + w2 * v2.z + w3 * v3.z;
            acc.w += w0 * v0.w + w1 * v1.w + w2 * v2.w + w3 * v3.w;
        }
        size_t rbase = (size_t)n * KTOT;
        float4 r = acc;
        if (mode) {
            uint2 qp = *(const uint2*)(g_T + rbase + slot_prev * F_IN + lane * 4);
            float4 tp = unpack_h4(qp);
            r.x = 2.f * acc.x - tp.x; r.y = 2.f * acc.y - tp.y;
            r.z = 2.f * acc.z - tp.z; r.w = 2.f * acc.w - tp.w;
        }
        *(uint2*)(g_T + rbase + slot_out * F_IN + lane * 4) = pack_h4(r);
    }
}

// ============================== GEMM (mma.sync fp16, W split) ==============
__global__ void __launch_bounds__(128) gemm_mma_kernel(
        const float* __restrict__ bias, float* __restrict__ out) {
    int wid = threadIdx.x >> 5, lane = threadIdx.x & 31;
    int warp = blockIdx.x * 4 + wid;
    if (warp >= NWARPS_GEMM) return;
    int row0 = warp * 32;
    int r  = lane >> 2;
    int cc = (lane & 3) * 2;

    int rr[4];
    rr[0] = min(row0      + r, N_NODES - 1);
    rr[1] = min(row0 +  8 + r, N_NODES - 1);
    rr[2] = min(row0 + 16 + r, N_NODES - 1);
    rr[3] = min(row0 + 24 + r, N_NODES - 1);

    float acc[2][8][4];
    #pragma unroll
    for (int m = 0; m < 2; m++)
        #pragma unroll
        for (int j = 0; j < 8; j++)
            #pragma unroll
            for (int q = 0; q < 4; q++) acc[m][j][q] = 0.f;

    for (int ks = 0; ks < NKSTEP; ks++) {
        int kt = ks * 16;
        uint32_t ah[2][4];
        #pragma unroll
        for (int m = 0; m < 2; m++) {
            const __half* p0 = g_T + (size_t)rr[2 * m    ] * KTOT + kt;
            const __half* p1 = g_T + (size_t)rr[2 * m + 1] * KTOT + kt;
            ah[m][0] = *(const uint32_t*)(p0 + cc);
            ah[m][1] = *(const uint32_t*)(p1 + cc);
            ah[m][2] = *(const uint32_t*)(p0 + cc + 8);
            ah[m][3] = *(const uint32_t*)(p1 + cc + 8);
        }
        const uint4* wp = g_Wpack + (size_t)ks * 8 * 32 + lane;
        #pragma unroll
        for (int j = 0; j < 8; j++) {
            uint4 bp = __ldg(wp + j * 32);
            uint32_t bh[2] = {bp.x, bp.y};
            uint32_t bl[2] = {bp.z, bp.w};
            mma16816(acc[0][j], ah[0], bh);
            mma16816(acc[0][j], ah[0], bl);
            mma16816(acc[1][j], ah[1], bh);
            mma16816(acc[1][j], ah[1], bl);
        }
    }

    #pragma unroll
    for (int m = 0; m < 2; m++) {
        int row_a = row0 + m * 16 + r;
        int row_b = row_a + 8;
        #pragma unroll
        for (int j = 0; j < 8; j++) {
            int col = j * 8 + cc;
            float b0 = __ldg(&bias[col]), b1 = __ldg(&bias[col + 1]);
            if (row_a < N_NODES) {
                float2 o;
                o.x = fmaxf(acc[m][j][0] + b0, 0.f);
                o.y = fmaxf(acc[m][j][1] + b1, 0.f);
                *(float2*)(out + (size_t)row_a * F_OUT + col) = o;
            }
            if (row_b < N_NODES) {
                float2 o;
                o.x = fmaxf(acc[m][j][2] + b0, 0.f);
                o.y = fmaxf(acc[m][j][3] + b1, 0.f);
                *(float2*)(out + (size_t)row_b * F_OUT + col) = o;
            }
        }
    }
}

// ---------------------------------------------------------------------------
extern "C" void kernel_launch(void* const* d_in, const int* in_sizes, int n_in,
                              void* d_out, int out_size) {
    const float* x  = (const float*)d_in[0];
    const void*  ei = d_in[1];
    const float* W  = (const float*)d_in[2];
    const float* b  = (const float*)d_in[3];
    float*       out = (float*)d_out;

    init_kernel<<<(N_NODES + 255) / 256, 256>>>((const unsigned int*)ei);
    decode_hist_kernel<<<(N_EDGES + 255) / 256, 256>>>(ei);
    scan_kernel<<<NBLK, SCAN_BLK>>>();
    scatter_kernel<<<(N_EDGES + 255) / 256, 256>>>();
    prep_kernel<<<PACKW_BLOCKS + (N_NODES * (F_IN / 4) + 255) / 256, 256>>>(W, x);

    // T1 = prop(T0); T_k = 2*prop(T_{k-1}) - T_{k-2}
    spmm_kernel<<<SPMM_BLOCKS, SPMM_THREADS>>>(0, -1, 1, 0);
    for (int k = 2; k < KORD; k++)
        spmm_kernel<<<SPMM_BLOCKS, SPMM_THREADS>>>(k - 1, k - 2, k, 1);

    gemm_mma_kernel<<<(NWARPS_GEMM + 3) / 4, 128>>>(b, out);
}

// round 9
// speedup vs baseline: 1.3429x; 1.3429x over previous
#include <cuda_runtime.h>
#include <cuda_fp16.h>
#include <cstdint>

// ChebConv K=8 on GB300 (sm_103 base target — mma.sync tensor path):
//  - decode edges (dtype-robust), build padded CSR by dst (3-phase scan)
//  - 7 SpMM propagations over an fp16 panel (fp32 accumulate) — L2-byte bound
//  - GEMM [50000,1024]x[1024,64] via mma.sync fp16 + bias + ReLU

#define N_NODES 50000
#define N_EDGES 800000
#define EPAD    (N_EDGES + 4 * N_NODES)
#define F_IN    128
#define F_OUT   64
#define KORD    8
#define KTOT    (KORD * F_IN)                // 1024
#define NKSTEP  (KTOT / 16)                  // 64
#define SCAN_BLK 1024
#define NBLK    ((N_NODES + SCAN_BLK - 1) / SCAN_BLK)   // 49
#define NWARPS_GEMM ((N_NODES + 31) / 32)               // 1563

// ---- scratch (static device globals; no allocations) ----
__device__ __align__(16) __half g_T[(size_t)N_NODES * KTOT];   // fp16 panel, slots k*128
__device__ __align__(16) uint2  g_Wpack[NKSTEP * 8 * 32];      // W^T frag {hi01, hi89}
__device__ int   g_is64;
__device__ int   g_cnt[N_NODES];
__device__ int   g_deg[N_NODES];
__device__ float g_dis[N_NODES];
__device__ int   g_rowptr[N_NODES + 1];
__device__ int   g_cursor[N_NODES];
__device__ int   g_bsum[NBLK];
__device__ int   g_boff[NBLK];
__device__ __align__(8) int2 g_edge[EPAD];   // {src, float_bits(w)}

// =================== helpers ===============================================
__device__ __forceinline__ void mma16816(float* c, const uint32_t* a, const uint32_t* b) {
    asm volatile(
        "mma.sync.aligned.m16n8k16.row.col.f32.f16.f16.f32 "
        "{%0,%1,%2,%3}, {%4,%5,%6,%7}, {%8,%9}, {%0,%1,%2,%3};"
        : "+f"(c[0]), "+f"(c[1]), "+f"(c[2]), "+f"(c[3])
        : "r"(a[0]), "r"(a[1]), "r"(a[2]), "r"(a[3]), "r"(b[0]), "r"(b[1]));
}
__device__ __forceinline__ uint32_t pack_h2(float a, float b) {
    __half2 h = __floats2half2_rn(a, b);
    return *reinterpret_cast<uint32_t*>(&h);
}
__device__ __forceinline__ float4 unpack_h4(uint2 q) {
    __half2 h0 = *reinterpret_cast<__half2*>(&q.x);
    __half2 h1 = *reinterpret_cast<__half2*>(&q.y);
    float2 f0 = __half22float2(h0), f1 = __half22float2(h1);
    return make_float4(f0.x, f0.y, f1.x, f1.y);
}
__device__ __forceinline__ uint2 pack_h4(float4 r) {
    uint2 q;
    q.x = pack_h2(r.x, r.y);
    q.y = pack_h2(r.z, r.w);
    return q;
}
// decode edge e from raw buffer (int32 or int64), clamped — used by 2 kernels
__device__ __forceinline__ void decode_edge(const void* ei, int e, int& s, int& d) {
    if (g_is64) {
        const long long* p = (const long long*)ei;
        s = (int)p[e]; d = (int)p[N_EDGES + e];
    } else {
        const int* p = (const int*)ei;
        s = p[e]; d = p[N_EDGES + e];
    }
    s = min(max(s, 0), N_NODES - 1);
    d = min(max(d, 0), N_NODES - 1);
}

// ============================ preprocessing ================================
__global__ void init_kernel(const unsigned int* __restrict__ p) {
    int i = blockIdx.x * blockDim.x + threadIdx.x;
    if (blockIdx.x == 0 && threadIdx.x < 32) {
        int lane = threadIdx.x;
        bool bad = false;
        #pragma unroll
        for (int j = 0; j < 8; j++)
            if (p[2 * (lane * 8 + j) + 1] != 0u) bad = true;
        unsigned m = __ballot_sync(0xffffffffu, bad);
        if (lane == 0) g_is64 = (m == 0u) ? 1 : 0;
    }
    if (i < N_NODES) { g_cnt[i] = 0; g_deg[i] = 0; }
}
__global__ void hist_kernel(const void* __restrict__ ei) {
    int e = blockIdx.x * blockDim.x + threadIdx.x;
    if (e < N_EDGES) {
        int s, d;
        decode_edge(ei, e, s, d);
        atomicAdd(&g_deg[s], 1);
        atomicAdd(&g_cnt[d], 1);
    }
}
__global__ void scan1_kernel() {
    __shared__ int wsum[32];
    int tid = threadIdx.x, lane = tid & 31, wid = tid >> 5;
    int i = blockIdx.x * SCAN_BLK + tid;
    int v = 0;
    if (i < N_NODES) {
        int d = g_deg[i];
        g_dis[i] = (d > 0) ? rsqrtf((float)d) : 0.0f;
        v = (g_cnt[i] + 3) & ~3;             // pad row to multiple of 4
    }
    int x = v;
    #pragma unroll
    for (int off = 1; off < 32; off <<= 1) {
        int t = __shfl_up_sync(0xffffffffu, x, off);
        if (lane >= off) x += t;
    }
    if (lane == 31) wsum[wid] = x;
    __syncthreads();
    if (wid == 0) {
        int y = wsum[lane];
        #pragma unroll
        for (int off = 1; off < 32; off <<= 1) {
            int t = __shfl_up_sync(0xffffffffu, y, off);
            if (lane >= off) y += t;
        }
        wsum[lane] = y;
    }
    __syncthreads();
    int excl = x - v + (wid > 0 ? wsum[wid - 1] : 0);
    if (i < N_NODES) g_rowptr[i] = excl;
    if (tid == 0) g_bsum[blockIdx.x] = wsum[31];
}
__global__ void scan2_kernel() {
    __shared__ int sh[64];
    int tid = threadIdx.x;
    int v = (tid < NBLK) ? g_bsum[tid] : 0;
    sh[tid] = v;
    __syncthreads();
    #pragma unroll
    for (int off = 1; off < 64; off <<= 1) {
        int t = (tid >= off) ? sh[tid - off] : 0;
        __syncthreads();
        sh[tid] += t;
        __syncthreads();
    }
    if (tid < NBLK) g_boff[tid] = sh[tid] - v;       // exclusive
    if (tid == NBLK - 1) g_rowptr[N_NODES] = sh[tid];
}
__global__ void scan3_kernel() {
    int i = blockIdx.x * blockDim.x + threadIdx.x;
    if (i < N_NODES) {
        int val = g_rowptr[i] + g_boff[i >> 10];
        g_rowptr[i] = val;
        g_cursor[i] = val;
        int cnt  = g_cnt[i];
        int cntp = (cnt + 3) & ~3;
        for (int j = cnt; j < cntp; j++)
            g_edge[val + j] = make_int2(0, 0);
    }
}
__global__ void scatter_kernel(const void* __restrict__ ei) {
    int e = blockIdx.x * blockDim.x + threadIdx.x;
    if (e < N_EDGES) {
        int s, d;
        decode_edge(ei, e, s, d);
        float w = -g_dis[s] * g_dis[d];
        int pos = atomicAdd(&g_cursor[d], 1);
        g_edge[pos] = make_int2(s, __float_as_int(w));
    }
}
// fused: blocks [0,64) pack W^T fp16 fragments; blocks [64,...) convert x -> fp16 slot 0
#define PACKW_BLOCKS 64
__global__ void prep_kernel(const float* __restrict__ W, const float* __restrict__ x) {
    if (blockIdx.x < PACKW_BLOCKS) {
        int i = blockIdx.x * 256 + threadIdx.x;      // < 16384
        int lane = i & 31, nt = (i >> 5) & 7, ks = i >> 8;
        int n  = nt * 8 + (lane >> 2);
        int k0 = ks * 16 + (lane & 3) * 2;
        float v00 = W[(size_t)(k0    ) * 64 + n];
        float v01 = W[(size_t)(k0 + 1) * 64 + n];
        float v10 = W[(size_t)(k0 + 8) * 64 + n];
        float v11 = W[(size_t)(k0 + 9) * 64 + n];
        uint2 p;
        p.x = pack_h2(v00, v01);
        p.y = pack_h2(v10, v11);
        g_Wpack[i] = p;
    } else {
        int i = (blockIdx.x - PACKW_BLOCKS) * 256 + threadIdx.x;  // float4 index
        if (i < N_NODES * (F_IN / 4)) {
            int row = i >> 5, c4 = i & 31;
            float4 v = __ldg((const float4*)x + i);
            *(uint2*)&g_T[(size_t)row * KTOT + c4 * 4] = pack_h4(v);   // slot 0
        }
    }
}

// ============================== SpMM =======================================
// warp-per-node, 32 lanes x 4 fp16 features (uint2 per edge-lane), fp32 accum.
// mode 0: T_out = prop(T_in);  mode 1: T_out = 2*prop(T_in) - T_prev
__global__ void spmm_kernel(int slot_in, int slot_prev, int slot_out, int mode) {
    int warp = blockIdx.x * (blockDim.x >> 5) + (threadIdx.x >> 5);
    if (warp >= N_NODES) return;
    int lane = threadIdx.x & 31;
    int beg = g_rowptr[warp], end = g_rowptr[warp + 1];
    int cin = slot_in * F_IN;
    float4 acc = make_float4(0.f, 0.f, 0.f, 0.f);
    #pragma unroll 2
    for (int e = beg; e < end; e += 4) {
        int2 ed0 = __ldg(&g_edge[e]);
        int2 ed1 = __ldg(&g_edge[e + 1]);
        int2 ed2 = __ldg(&g_edge[e + 2]);
        int2 ed3 = __ldg(&g_edge[e + 3]);
        uint2 q0 = __ldg((const uint2*)(g_T + (size_t)ed0.x * KTOT + cin) + lane);
        uint2 q1 = __ldg((const uint2*)(g_T + (size_t)ed1.x * KTOT + cin) + lane);
        uint2 q2 = __ldg((const uint2*)(g_T + (size_t)ed2.x * KTOT + cin) + lane);
        uint2 q3 = __ldg((const uint2*)(g_T + (size_t)ed3.x * KTOT + cin) + lane);
        float w0 = __int_as_float(ed0.y), w1 = __int_as_float(ed1.y);
        float w2 = __int_as_float(ed2.y), w3 = __int_as_float(ed3.y);
        float4 v0 = unpack_h4(q0);
        float4 v1 = unpack_h4(q1);
        float4 v2 = unpack_h4(q2);
        float4 v3 = unpack_h4(q3);
        acc.x += w0 * v0.x + w1 * v1.x + w2 * v2.x + w3 * v3.x;
        acc.y += w0 * v0.y + w1 * v1.y + w2 * v2.y + w3 * v3.y;
        acc.z += w0 * v0.z + w1 * v1.z + w2 * v2.z + w3 * v3.z;
        acc.w += w0 * v0.w + w1 * v1.w + w2 * v2.w + w3 * v3.w;
    }
    size_t rbase = (size_t)warp * KTOT;
    float4 r = acc;
    if (mode) {
        uint2 qp = *(const uint2*)(g_T + rbase + slot_prev * F_IN + lane * 4);
        float4 tp = unpack_h4(qp);
        r.x = 2.f * acc.x - tp.x; r.y = 2.f * acc.y - tp.y;
        r.z = 2.f * acc.z - tp.z; r.w = 2.f * acc.w - tp.w;
    }
    *(uint2*)(g_T + rbase + slot_out * F_IN + lane * 4) = pack_h4(r);
}

// ============================== GEMM (mma.sync fp16) =======================
__global__ void __launch_bounds__(128) gemm_mma_kernel(
        const float* __restrict__ bias, float* __restrict__ out) {
    int wid = threadIdx.x >> 5, lane = threadIdx.x & 31;
    int warp = blockIdx.x * 4 + wid;
    if (warp >= NWARPS_GEMM) return;
    int row0 = warp * 32;
    int r  = lane >> 2;
    int cc = (lane & 3) * 2;

    int rr[4];
    rr[0] = min(row0      + r, N_NODES - 1);
    rr[1] = min(row0 +  8 + r, N_NODES - 1);
    rr[2] = min(row0 + 16 + r, N_NODES - 1);
    rr[3] = min(row0 + 24 + r, N_NODES - 1);

    float acc[2][8][4];
    #pragma unroll
    for (int m = 0; m < 2; m++)
        #pragma unroll
        for (int j = 0; j < 8; j++)
            #pragma unroll
            for (int q = 0; q < 4; q++) acc[m][j][q] = 0.f;

    for (int ks = 0; ks < NKSTEP; ks++) {
        int kt = ks * 16;
        uint32_t ah[2][4];
        #pragma unroll
        for (int m = 0; m < 2; m++) {
            const __half* p0 = g_T + (size_t)rr[2 * m    ] * KTOT + kt;
            const __half* p1 = g_T + (size_t)rr[2 * m + 1] * KTOT + kt;
            ah[m][0] = *(const uint32_t*)(p0 + cc);
            ah[m][1] = *(const uint32_t*)(p1 + cc);
            ah[m][2] = *(const uint32_t*)(p0 + cc + 8);
            ah[m][3] = *(const uint32_t*)(p1 + cc + 8);
        }
        const uint2* wp = g_Wpack + (size_t)ks * 8 * 32 + lane;
        #pragma unroll
        for (int j = 0; j < 8; j++) {
            uint2 bp = __ldg(wp + j * 32);
            uint32_t bh[2] = {bp.x, bp.y};
            mma16816(acc[0][j], ah[0], bh);
            mma16816(acc[1][j], ah[1], bh);
        }
    }

    #pragma unroll
    for (int m = 0; m < 2; m++) {
        int row_a = row0 + m * 16 + r;
        int row_b = row_a + 8;
        #pragma unroll
        for (int j = 0; j < 8; j++) {
            int col = j * 8 + cc;
            float b0 = __ldg(&bias[col]), b1 = __ldg(&bias[col + 1]);
            if (row_a < N_NODES) {
                float2 o;
                o.x = fmaxf(acc[m][j][0] + b0, 0.f);
                o.y = fmaxf(acc[m][j][1] + b1, 0.f);
                *(float2*)(out + (size_t)row_a * F_OUT + col) = o;
            }
            if (row_b < N_NODES) {
                float2 o;
                o.x = fmaxf(acc[m][j][2] + b0, 0.f);
                o.y = fmaxf(acc[m][j][3] + b1, 0.f);
                *(float2*)(out + (size_t)row_b * F_OUT + col) = o;
            }
        }
    }
}

// ---------------------------------------------------------------------------
extern "C" void kernel_launch(void* const* d_in, const int* in_sizes, int n_in,
                              void* d_out, int out_size) {
    const float* x  = (const float*)d_in[0];
    const void*  ei = d_in[1];
    const float* W  = (const float*)d_in[2];
    const float* b  = (const float*)d_in[3];
    float*       out = (float*)d_out;

    init_kernel<<<(N_NODES + 255) / 256, 256>>>((const unsigned int*)ei);
    hist_kernel<<<(N_EDGES + 255) / 256, 256>>>(ei);
    scan1_kernel<<<NBLK, SCAN_BLK>>>();
    scan2_kernel<<<1, 64>>>();
    scan3_kernel<<<(N_NODES + 255) / 256, 256>>>();
    scatter_kernel<<<(N_EDGES + 255) / 256, 256>>>(ei);
    prep_kernel<<<PACKW_BLOCKS + (N_NODES * (F_IN / 4) + 255) / 256, 256>>>(W, x);

    // T1 = prop(T0); T_k = 2*prop(T_{k-1}) - T_{k-2}
    spmm_kernel<<<(N_NODES + 7) / 8, 256>>>(0, -1, 1, 0);
    for (int k = 2; k < KORD; k++)
        spmm_kernel<<<(N_NODES + 7) / 8, 256>>>(k - 1, k - 2, k, 1);

    gemm_mma_kernel<<<(NWARPS_GEMM + 3) / 4, 128>>>(b, out);
}

// round 10
// speedup vs baseline: 1.6395x; 1.2209x over previous
#include <cuda_runtime.h>
#include <cuda_fp16.h>
#include <cstdint>

// ChebConv K=8 on GB300 — Clenshaw form:
//   Z_k = x @ W_k   (one fp16 mma GEMM [50000,128]x[128,512])
//   b_7 = Z_7;  b_k = 2 L_hat b_{k+1} - b_{k+2} + Z_k   (k=6..1, 64-dim props)
//   out = relu(L_hat b_1 - b_2 + Z_0 + bias)            (final 64-dim prop)
// Propagations are 64-wide (half the gather bytes of the T_k recurrence).

#define N_NODES 50000
#define N_EDGES 800000
#define EPAD    (N_EDGES + 4 * N_NODES)
#define F_IN    128
#define F_OUT   64
#define KORD    8
#define ZTOT    (KORD * F_OUT)               // 512 (8 slots x 64)
#define SCAN_BLK 1024
#define NBLK    ((N_NODES + SCAN_BLK - 1) / SCAN_BLK)   // 49
#define GEMM_BLOCKS ((N_NODES + 31) / 32)               // 1563

// ---- scratch (static device globals; no allocations) ----
__device__ __align__(16) __half g_T[(size_t)N_NODES * ZTOT];  // Z/b slots, 64 each
__device__ __align__(16) __half g_X16[(size_t)N_NODES * F_IN];
__device__ __align__(16) uint2  g_Wpack[8 * 64 * 32];         // [kstep][ntile][lane]
__device__ int   g_is64;
__device__ int   g_cnt[N_NODES];
__device__ int   g_deg[N_NODES];
__device__ float g_dis[N_NODES];
__device__ int   g_rowptr[N_NODES + 1];
__device__ int   g_cursor[N_NODES];
__device__ int   g_bsum[NBLK];
__device__ int   g_boff[NBLK];
__device__ __align__(8) int2 g_edge[EPAD];   // {src, float_bits(w)}

// =================== helpers ===============================================
__device__ __forceinline__ void mma16816(float* c, const uint32_t* a, const uint32_t* b) {
    asm volatile(
        "mma.sync.aligned.m16n8k16.row.col.f32.f16.f16.f32 "
        "{%0,%1,%2,%3}, {%4,%5,%6,%7}, {%8,%9}, {%0,%1,%2,%3};"
        : "+f"(c[0]), "+f"(c[1]), "+f"(c[2]), "+f"(c[3])
        : "r"(a[0]), "r"(a[1]), "r"(a[2]), "r"(a[3]), "r"(b[0]), "r"(b[1]));
}
__device__ __forceinline__ uint32_t pack_h2(float a, float b) {
    __half2 h = __floats2half2_rn(a, b);
    return *reinterpret_cast<uint32_t*>(&h);
}
__device__ __forceinline__ float2 unpack_h2(uint32_t q) {
    __half2 h = *reinterpret_cast<__half2*>(&q);
    return __half22float2(h);
}
__device__ __forceinline__ uint2 pack_h4(float4 r) {
    uint2 q;
    q.x = pack_h2(r.x, r.y);
    q.y = pack_h2(r.z, r.w);
    return q;
}
__device__ __forceinline__ void decode_edge(const void* ei, int e, int& s, int& d) {
    if (g_is64) {
        const long long* p = (const long long*)ei;
        s = (int)p[e]; d = (int)p[N_EDGES + e];
    } else {
        const int* p = (const int*)ei;
        s = p[e]; d = p[N_EDGES + e];
    }
    s = min(max(s, 0), N_NODES - 1);
    d = min(max(d, 0), N_NODES - 1);
}

// ============================ preprocessing ================================
__global__ void init_kernel(const unsigned int* __restrict__ p) {
    int i = blockIdx.x * blockDim.x + threadIdx.x;
    if (blockIdx.x == 0 && threadIdx.x < 32) {
        int lane = threadIdx.x;
        bool bad = false;
        #pragma unroll
        for (int j = 0; j < 8; j++)
            if (p[2 * (lane * 8 + j) + 1] != 0u) bad = true;
        unsigned m = __ballot_sync(0xffffffffu, bad);
        if (lane == 0) g_is64 = (m == 0u) ? 1 : 0;
    }
    if (i < N_NODES) { g_cnt[i] = 0; g_deg[i] = 0; }
}
__global__ void hist_kernel(const void* __restrict__ ei) {
    int e = blockIdx.x * blockDim.x + threadIdx.x;
    if (e < N_EDGES) {
        int s, d;
        decode_edge(ei, e, s, d);
        atomicAdd(&g_deg[s], 1);
        atomicAdd(&g_cnt[d], 1);
    }
}
__global__ void scan1_kernel() {
    __shared__ int wsum[32];
    int tid = threadIdx.x, lane = tid & 31, wid = tid >> 5;
    int i = blockIdx.x * SCAN_BLK + tid;
    int v = 0;
    if (i < N_NODES) {
        int d = g_deg[i];
        g_dis[i] = (d > 0) ? rsqrtf((float)d) : 0.0f;
        v = (g_cnt[i] + 3) & ~3;
    }
    int x = v;
    #pragma unroll
    for (int off = 1; off < 32; off <<= 1) {
        int t = __shfl_up_sync(0xffffffffu, x, off);
        if (lane >= off) x += t;
    }
    if (lane == 31) wsum[wid] = x;
    __syncthreads();
    if (wid == 0) {
        int y = wsum[lane];
        #pragma unroll
        for (int off = 1; off < 32; off <<= 1) {
            int t = __shfl_up_sync(0xffffffffu, y, off);
            if (lane >= off) y += t;
        }
        wsum[lane] = y;
    }
    __syncthreads();
    int excl = x - v + (wid > 0 ? wsum[wid - 1] : 0);
    if (i < N_NODES) g_rowptr[i] = excl;
    if (tid == 0) g_bsum[blockIdx.x] = wsum[31];
}
__global__ void scan2_kernel() {
    __shared__ int sh[64];
    int tid = threadIdx.x;
    int v = (tid < NBLK) ? g_bsum[tid] : 0;
    sh[tid] = v;
    __syncthreads();
    #pragma unroll
    for (int off = 1; off < 64; off <<= 1) {
        int t = (tid >= off) ? sh[tid - off] : 0;
        __syncthreads();
        sh[tid] += t;
        __syncthreads();
    }
    if (tid < NBLK) g_boff[tid] = sh[tid] - v;
    if (tid == NBLK - 1) g_rowptr[N_NODES] = sh[tid];
}
__global__ void scan3_kernel() {
    int i = blockIdx.x * blockDim.x + threadIdx.x;
    if (i < N_NODES) {
        int val = g_rowptr[i] + g_boff[i >> 10];
        g_rowptr[i] = val;
        g_cursor[i] = val;
        int cnt  = g_cnt[i];
        int cntp = (cnt + 3) & ~3;
        for (int j = cnt; j < cntp; j++)
            g_edge[val + j] = make_int2(0, 0);
    }
}
__global__ void scatter_kernel(const void* __restrict__ ei) {
    int e = blockIdx.x * blockDim.x + threadIdx.x;
    if (e < N_EDGES) {
        int s, d;
        decode_edge(ei, e, s, d);
        float w = -g_dis[s] * g_dis[d];
        int pos = atomicAdd(&g_cursor[d], 1);
        g_edge[pos] = make_int2(s, __float_as_int(w));
    }
}
// fused: blocks [0,64) pack Wcat^T fragments; blocks [64,...) x -> fp16
// Wcat col n (0..511): order o=n>>6, j2=n&63; Wcat(n,k) = W[o*8192 + k*64 + j2]
#define PACKW_BLOCKS 64
__global__ void prep_kernel(const float* __restrict__ W, const float* __restrict__ x) {
    if (blockIdx.x < PACKW_BLOCKS) {
        int i = blockIdx.x * 256 + threadIdx.x;      // < 16384 = 8ks*64nt*32ln
        int lane = i & 31, nt = (i >> 5) & 63, ks = i >> 11;
        int n  = nt * 8 + (lane >> 2);               // col in 0..511
        int k0 = ks * 16 + (lane & 3) * 2;
        int o = n >> 6, j2 = n & 63;
        const float* Wb = W + (size_t)o * (F_IN * F_OUT) + j2;
        float v00 = Wb[(size_t)(k0    ) * 64];
        float v01 = Wb[(size_t)(k0 + 1) * 64];
        float v10 = Wb[(size_t)(k0 + 8) * 64];
        float v11 = Wb[(size_t)(k0 + 9) * 64];
        uint2 p;
        p.x = pack_h2(v00, v01);
        p.y = pack_h2(v10, v11);
        g_Wpack[i] = p;
    } else {
        int i = (blockIdx.x - PACKW_BLOCKS) * 256 + threadIdx.x;  // float4 index
        if (i < N_NODES * (F_IN / 4)) {
            float4 v = __ldg((const float4*)x + i);
            *(uint2*)&g_X16[(size_t)i * 4] = pack_h4(v);
        }
    }
}

// ===================== GEMM Z = x @ Wcat (mma.sync fp16) ===================
// block: 256 threads = 8 warps; rows [blk*32,+32); warp w -> cols [w*64,+64)
__global__ void __launch_bounds__(256) gemmz_kernel() {
    int wid = threadIdx.x >> 5, lane = threadIdx.x & 31;
    int row0 = blockIdx.x * 32;
    int r  = lane >> 2;
    int cc = (lane & 3) * 2;

    int rr[4];
    rr[0] = min(row0      + r, N_NODES - 1);
    rr[1] = min(row0 +  8 + r, N_NODES - 1);
    rr[2] = min(row0 + 16 + r, N_NODES - 1);
    rr[3] = min(row0 + 24 + r, N_NODES - 1);

    float acc[2][8][4];
    #pragma unroll
    for (int m = 0; m < 2; m++)
        #pragma unroll
        for (int j = 0; j < 8; j++)
            #pragma unroll
            for (int q = 0; q < 4; q++) acc[m][j][q] = 0.f;

    #pragma unroll
    for (int ks = 0; ks < 8; ks++) {                  // K = 128
        int kt = ks * 16;
        uint32_t ah[2][4];
        #pragma unroll
        for (int m = 0; m < 2; m++) {
            const __half* p0 = g_X16 + (size_t)rr[2 * m    ] * F_IN + kt;
            const __half* p1 = g_X16 + (size_t)rr[2 * m + 1] * F_IN + kt;
            ah[m][0] = *(const uint32_t*)(p0 + cc);
            ah[m][1] = *(const uint32_t*)(p1 + cc);
            ah[m][2] = *(const uint32_t*)(p0 + cc + 8);
            ah[m][3] = *(const uint32_t*)(p1 + cc + 8);
        }
        const uint2* wp = g_Wpack + ((size_t)ks * 64 + wid * 8) * 32 + lane;
        #pragma unroll
        for (int j = 0; j < 8; j++) {
            uint2 bp = __ldg(wp + j * 32);
            uint32_t bh[2] = {bp.x, bp.y};
            mma16816(acc[0][j], ah[0], bh);
            mma16816(acc[1][j], ah[1], bh);
        }
    }
    // store Z as fp16 into g_T
    #pragma unroll
    for (int m = 0; m < 2; m++) {
        int row_a = row0 + m * 16 + r;
        int row_b = row_a + 8;
        #pragma unroll
        for (int j = 0; j < 8; j++) {
            int col = wid * 64 + j * 8 + cc;
            if (row_a < N_NODES)
                *(uint32_t*)&g_T[(size_t)row_a * ZTOT + col] = pack_h2(acc[m][j][0], acc[m][j][1]);
            if (row_b < N_NODES)
                *(uint32_t*)&g_T[(size_t)row_b * ZTOT + col] = pack_h2(acc[m][j][2], acc[m][j][3]);
        }
    }
}

// ===================== Clenshaw propagation (64-dim) =======================
// b_out(slot_z) = 2 * L_hat b(slot_g) - b(slot_b2) + Z(slot_z); slot_b2<0 -> 0
__global__ void cheb_kernel(int slot_g, int slot_b2, int slot_z) {
    int warp = blockIdx.x * (blockDim.x >> 5) + (threadIdx.x >> 5);
    if (warp >= N_NODES) return;
    int lane = threadIdx.x & 31;
    int beg = g_rowptr[warp], end = g_rowptr[warp + 1];
    int cg = slot_g * F_OUT + lane * 2;
    float2 acc = make_float2(0.f, 0.f);
    #pragma unroll 2
    for (int e = beg; e < end; e += 4) {
        int2 ed0 = __ldg(&g_edge[e]);
        int2 ed1 = __ldg(&g_edge[e + 1]);
        int2 ed2 = __ldg(&g_edge[e + 2]);
        int2 ed3 = __ldg(&g_edge[e + 3]);
        uint32_t q0 = *(const uint32_t*)(g_T + (size_t)ed0.x * ZTOT + cg);
        uint32_t q1 = *(const uint32_t*)(g_T + (size_t)ed1.x * ZTOT + cg);
        uint32_t q2 = *(const uint32_t*)(g_T + (size_t)ed2.x * ZTOT + cg);
        uint32_t q3 = *(const uint32_t*)(g_T + (size_t)ed3.x * ZTOT + cg);
        float w0 = __int_as_float(ed0.y), w1 = __int_as_float(ed1.y);
        float w2 = __int_as_float(ed2.y), w3 = __int_as_float(ed3.y);
        float2 v0 = unpack_h2(q0), v1 = unpack_h2(q1);
        float2 v2 = unpack_h2(q2), v3 = unpack_h2(q3);
        acc.x += w0 * v0.x + w1 * v1.x + w2 * v2.x + w3 * v3.x;
        acc.y += w0 * v0.y + w1 * v1.y + w2 * v2.y + w3 * v3.y;
    }
    size_t rbase = (size_t)warp * ZTOT;
    float2 z = unpack_h2(*(const uint32_t*)(g_T + rbase + slot_z * F_OUT + lane * 2));
    float2 r;
    if (slot_b2 >= 0) {
        float2 b2 = unpack_h2(*(const uint32_t*)(g_T + rbase + slot_b2 * F_OUT + lane * 2));
        r.x = 2.f * acc.x - b2.x + z.x;
        r.y = 2.f * acc.y - b2.y + z.y;
    } else {
        r.x = 2.f * acc.x + z.x;
        r.y = 2.f * acc.y + z.y;
    }
    *(uint32_t*)(g_T + rbase + slot_z * F_OUT + lane * 2) = pack_h2(r.x, r.y);
}

// out = relu(L_hat b(slot1) - b(slot2) + Z(slot0) + bias), fp32 output
__global__ void final_kernel(const float* __restrict__ bias, float* __restrict__ out) {
    int warp = blockIdx.x * (blockDim.x >> 5) + (threadIdx.x >> 5);
    if (warp >= N_NODES) return;
    int lane = threadIdx.x & 31;
    int beg = g_rowptr[warp], end = g_rowptr[warp + 1];
    int cg = 1 * F_OUT + lane * 2;
    float2 acc = make_float2(0.f, 0.f);
    #pragma unroll 2
    for (int e = beg; e < end; e += 4) {
        int2 ed0 = __ldg(&g_edge[e]);
        int2 ed1 = __ldg(&g_edge[e + 1]);
        int2 ed2 = __ldg(&g_edge[e + 2]);
        int2 ed3 = __ldg(&g_edge[e + 3]);
        uint32_t q0 = *(const uint32_t*)(g_T + (size_t)ed0.x * ZTOT + cg);
        uint32_t q1 = *(const uint32_t*)(g_T + (size_t)ed1.x * ZTOT + cg);
        uint32_t q2 = *(const uint32_t*)(g_T + (size_t)ed2.x * ZTOT + cg);
        uint32_t q3 = *(const uint32_t*)(g_T + (size_t)ed3.x * ZTOT + cg);
        float w0 = __int_as_float(ed0.y), w1 = __int_as_float(ed1.y);
        float w2 = __int_as_float(ed2.y), w3 = __int_as_float(ed3.y);
        float2 v0 = unpack_h2(q0), v1 = unpack_h2(q1);
        float2 v2 = unpack_h2(q2), v3 = unpack_h2(q3);
        acc.x += w0 * v0.x + w1 * v1.x + w2 * v2.x + w3 * v3.x;
        acc.y += w0 * v0.y + w1 * v1.y + w2 * v2.y + w3 * v3.y;
    }
    size_t rbase = (size_t)warp * ZTOT;
    float2 z0 = unpack_h2(*(const uint32_t*)(g_T + rbase + 0 * F_OUT + lane * 2));
    float2 b2 = unpack_h2(*(const uint32_t*)(g_T + rbase + 2 * F_OUT + lane * 2));
    float2 bv = *(const float2*)(bias + lane * 2);
    float2 o;
    o.x = fmaxf(acc.x - b2.x + z0.x + bv.x, 0.f);
    o.y = fmaxf(acc.y - b2.y + z0.y + bv.y, 0.f);
    *(float2*)(out + (size_t)warp * F_OUT + lane * 2) = o;
}

// ---------------------------------------------------------------------------
extern "C" void kernel_launch(void* const* d_in, const int* in_sizes, int n_in,
                              void* d_out, int out_size) {
    const float* x  = (const float*)d_in[0];
    const void*  ei = d_in[1];
    const float* W  = (const float*)d_in[2];
    const float* b  = (const float*)d_in[3];
    float*       out = (float*)d_out;

    init_kernel<<<(N_NODES + 255) / 256, 256>>>((const unsigned int*)ei);
    hist_kernel<<<(N_EDGES + 255) / 256, 256>>>(ei);
    scan1_kernel<<<NBLK, SCAN_BLK>>>();
    scan2_kernel<<<1, 64>>>();
    scan3_kernel<<<(N_NODES + 255) / 256, 256>>>();
    scatter_kernel<<<(N_EDGES + 255) / 256, 256>>>(ei);
    prep_kernel<<<PACKW_BLOCKS + (N_NODES * (F_IN / 4) + 255) / 256, 256>>>(W, x);

    gemmz_kernel<<<GEMM_BLOCKS, 256>>>();

    // Clenshaw: b_7 = Z_7 (in place); b_k = 2 L b_{k+1} - b_{k+2} + Z_k
    cheb_kernel<<<(N_NODES + 7) / 8, 256>>>(7, -1, 6);   // k=6 (b_8 = 0)
    cheb_kernel<<<(N_NODES + 7) / 8, 256>>>(6,  7, 5);   // k=5
    cheb_kernel<<<(N_NODES + 7) / 8, 256>>>(5,  6, 4);   // k=4
    cheb_kernel<<<(N_NODES + 7) / 8, 256>>>(4,  5, 3);   // k=3
    cheb_kernel<<<(N_NODES + 7) / 8, 256>>>(3,  4, 2);   // k=2
    cheb_kernel<<<(N_NODES + 7) / 8, 256>>>(2,  3, 1);   // k=1
    final_kernel<<<(N_NODES + 7) / 8, 256>>>(b, out);    // out = L b_1 - b_2 + Z_0
}